// round 8
// baseline (speedup 1.0000x reference)
#include <cuda_runtime.h>
#include <math.h>
#include <stdint.h>

#define NT 256
#define NW 8

// ---------------- scratch (device globals, no allocation) ----------------
__device__ float g_P[524288];      // split-K partials (max 2MB)
__device__ float g_qs[32768];      // q self  [B, H*64]
__device__ float g_knew[32768];
__device__ float g_vnew[32768];
__device__ float g_qe[32768];      // q enc
__device__ float g_attn_s[32768];  // self-attn head-concat out
__device__ float g_attn_e[32768];
__device__ float g_x1[32768];      // after self-attn LN
__device__ float g_x2[32768];      // after cross-attn LN
__device__ float g_h[131072];      // ffn hidden [32,4096]

// ---------------- small GEMM: C[32,N] = A[32,K] @ W, split-K partials ----
// headed=1: W is [H][K][64] (per-head row-major, head = n-tile)
// headed=0: W is [K][N] row-major
__global__ void gemm32(const float* __restrict__ A, const float* __restrict__ W,
                       float* __restrict__ P, int K, int N, int kchunk, int headed)
{
    __shared__ float As[32][32];
    int bn = blockIdx.x, bk = blockIdx.y;
    int tid = threadIdx.x;
    int n = tid & 63, bg = tid >> 6;          // 4 groups of 8 batch rows
    const float* Wt;
    size_t ldw;
    if (headed) { Wt = W + (size_t)bn * K * 64 + n; ldw = 64; }
    else        { Wt = W + (size_t)bn * 64 + n;     ldw = (size_t)N; }
    int k0 = bk * kchunk, k1 = min(K, k0 + kchunk);
    float acc[8];
    #pragma unroll
    for (int i = 0; i < 8; i++) acc[i] = 0.f;

    for (int kb = k0; kb < k1; kb += 32) {
        __syncthreads();
        for (int i = tid; i < 1024; i += NT) {
            int b = i >> 5, kk = i & 31;
            As[b][kk] = A[(size_t)b * K + kb + kk];
        }
        __syncthreads();
        const float* wp = Wt + (size_t)kb * ldw;
        #pragma unroll
        for (int kk = 0; kk < 32; kk++) {
            float w = wp[(size_t)kk * ldw];
            #pragma unroll
            for (int i = 0; i < 8; i++) acc[i] += As[bg * 8 + i][kk] * w;
        }
    }
    #pragma unroll
    for (int i = 0; i < 8; i++)
        P[((size_t)bk * 32 + bg * 8 + i) * N + (size_t)bn * 64 + n] = acc[i];
}

// ---------------- split-K reducers ----------------
__global__ void reduce_sum_k(const float* __restrict__ P, float* __restrict__ out,
                             int total, int stride, int KS)
{
    int i = blockIdx.x * blockDim.x + threadIdx.x;
    if (i >= total) return;
    float v = 0.f;
    for (int s = 0; s < KS; s++) v += P[(size_t)s * stride + i];
    out[i] = v;
}

__global__ void reduce_bias_relu(const float* __restrict__ P, const float* __restrict__ bias,
                                 float* __restrict__ out, int total, int stride, int KS, int N)
{
    int i = blockIdx.x * blockDim.x + threadIdx.x;
    if (i >= total) return;
    float v = bias[i % N];
    for (int s = 0; s < KS; s++) v += P[(size_t)s * stride + i];
    out[i] = fmaxf(v, 0.f);
}

// ---------------- sum partials + bias + residual, then LayerNorm ----------
__global__ void ln_finish(const float* __restrict__ P, int KS,
                          const float* __restrict__ bias, const float* __restrict__ res,
                          const float* __restrict__ gam, const float* __restrict__ bet,
                          float* __restrict__ out)
{
    __shared__ float row[1024];
    __shared__ float redm[NW], redv[NW];
    __shared__ float sh_mean, sh_rstd;
    int b = blockIdx.x, tid = threadIdx.x, lane = tid & 31, wid = tid >> 5;
    float lsum = 0.f, lsq = 0.f;
    for (int c = tid; c < 1024; c += NT) {
        float v = bias[c] + res[(size_t)b * 1024 + c];
        for (int s2 = 0; s2 < KS; s2++)
            v += P[((size_t)s2 * 32 + b) * 1024 + c];
        row[c] = v;
        lsum += v; lsq += v * v;
    }
    #pragma unroll
    for (int o = 16; o; o >>= 1) {
        lsum += __shfl_xor_sync(0xffffffffu, lsum, o);
        lsq  += __shfl_xor_sync(0xffffffffu, lsq, o);
    }
    if (!lane) { redm[wid] = lsum; redv[wid] = lsq; }
    __syncthreads();
    if (wid == 0) {
        float a  = (lane < NW) ? redm[lane] : 0.f;
        float c2 = (lane < NW) ? redv[lane] : 0.f;
        #pragma unroll
        for (int o = 4; o; o >>= 1) {
            a  += __shfl_xor_sync(0xffffffffu, a, o);
            c2 += __shfl_xor_sync(0xffffffffu, c2, o);
        }
        if (!lane) {
            float mean = a * (1.f / 1024.f);
            float var  = c2 * (1.f / 1024.f) - mean * mean;
            sh_mean = mean;
            sh_rstd = rsqrtf(var + 1e-6f);
        }
    }
    __syncthreads();
    float mean = sh_mean, rstd = sh_rstd;
    for (int c = tid; c < 1024; c += NT)
        out[(size_t)b * 1024 + c] = (row[c] - mean) * rstd * gam[c] + bet[c];
}

// ---------------- attention: one block per (b,h) -------------------------
// q: [B, H*64]; Kc/Vc: [B,H,Tc,64]; knew/vnew (optional): [B, H*64]
// probs: [B,H,T]; outv: [B, H*64]; T = Tc (+1 if knew)
__global__ void attn_kernel(const float* __restrict__ q,
                            const float* __restrict__ Kc,
                            const float* __restrict__ Vc,
                            const float* __restrict__ knew,
                            const float* __restrict__ vnew,
                            const uint8_t* __restrict__ mask,
                            float* __restrict__ probs,
                            float* __restrict__ outv,
                            int T, int Tc)
{
    __shared__ float s[2048];
    __shared__ float red[NW];
    __shared__ float red2[256];
    __shared__ float sh_max, sh_sum;
    int bh = blockIdx.x;
    int b = bh >> 4;
    int h = bh & 15;
    int tid = threadIdx.x, lane = tid & 31, wid = tid >> 5;
    size_t base = (size_t)bh * Tc * 64;
    float2 q2 = reinterpret_cast<const float2*>(q + (size_t)bh * 64)[lane];

    // ---- scores over cached keys: warp-per-row, 4 rows in flight ----
    for (int t0 = wid * 4; t0 < Tc; t0 += NW * 4) {
        float d[4] = {0.f, 0.f, 0.f, 0.f};
        #pragma unroll
        for (int j = 0; j < 4; j++) {
            if (t0 + j < Tc) {
                float2 kv = reinterpret_cast<const float2*>(Kc + base + (size_t)(t0 + j) * 64)[lane];
                d[j] = kv.x * q2.x + kv.y * q2.y;
            }
        }
        #pragma unroll
        for (int j = 0; j < 4; j++) {
            float v = d[j];
            v += __shfl_xor_sync(0xffffffffu, v, 16);
            v += __shfl_xor_sync(0xffffffffu, v, 8);
            v += __shfl_xor_sync(0xffffffffu, v, 4);
            v += __shfl_xor_sync(0xffffffffu, v, 2);
            v += __shfl_xor_sync(0xffffffffu, v, 1);
            if (lane == 0 && t0 + j < Tc) s[t0 + j] = v;
        }
    }
    // ---- new-token key (self-attn only) ----
    if (knew && wid == 0) {
        float2 kv = reinterpret_cast<const float2*>(knew + (size_t)bh * 64)[lane];
        float v = kv.x * q2.x + kv.y * q2.y;
        v += __shfl_xor_sync(0xffffffffu, v, 16);
        v += __shfl_xor_sync(0xffffffffu, v, 8);
        v += __shfl_xor_sync(0xffffffffu, v, 4);
        v += __shfl_xor_sync(0xffffffffu, v, 2);
        v += __shfl_xor_sync(0xffffffffu, v, 1);
        if (lane == 0) s[Tc] = v;
    }
    __syncthreads();

    // ---- scale + mask + max ----
    float lmax = -INFINITY;
    for (int t = tid; t < T; t += NT) {
        float v = s[t] * 0.125f;                 // 1/sqrt(64)
        if (mask[(size_t)b * T + t]) v = -INFINITY;
        s[t] = v;
        lmax = fmaxf(lmax, v);
    }
    #pragma unroll
    for (int o = 16; o; o >>= 1) lmax = fmaxf(lmax, __shfl_xor_sync(0xffffffffu, lmax, o));
    if (lane == 0) red[wid] = lmax;
    __syncthreads();
    if (wid == 0) {
        float m = (lane < NW) ? red[lane] : -INFINITY;
        #pragma unroll
        for (int o = 4; o; o >>= 1) m = fmaxf(m, __shfl_xor_sync(0xffffffffu, m, o));
        if (lane == 0) sh_max = m;
    }
    __syncthreads();
    float gmax = sh_max;

    // ---- exp + sum ----
    float lsum = 0.f;
    for (int t = tid; t < T; t += NT) {
        float e = __expf(s[t] - gmax);
        s[t] = e;
        lsum += e;
    }
    #pragma unroll
    for (int o = 16; o; o >>= 1) lsum += __shfl_xor_sync(0xffffffffu, lsum, o);
    if (lane == 0) red[wid] = lsum;
    __syncthreads();
    if (wid == 0) {
        float m = (lane < NW) ? red[lane] : 0.f;
        #pragma unroll
        for (int o = 4; o; o >>= 1) m += __shfl_xor_sync(0xffffffffu, m, o);
        if (lane == 0) sh_sum = m;
    }
    __syncthreads();
    float inv = 1.f / sh_sum;

    // ---- write normalized probs ----
    for (int t = tid; t < T; t += NT)
        probs[(size_t)bh * T + t] = s[t] * inv;

    // ---- weighted V sum: 4 t-groups x 64 columns, 4 accumulators ----
    int vcol = tid & 63, g = tid >> 6;
    const float* Vb = Vc + base + vcol;
    float a0 = 0.f, a1 = 0.f, a2 = 0.f, a3 = 0.f;
    int t = g;
    for (; t + 12 < Tc; t += 16) {
        a0 += s[t]      * Vb[(size_t)t * 64];
        a1 += s[t + 4]  * Vb[(size_t)(t + 4) * 64];
        a2 += s[t + 8]  * Vb[(size_t)(t + 8) * 64];
        a3 += s[t + 12] * Vb[(size_t)(t + 12) * 64];
    }
    for (; t < Tc; t += 4) a0 += s[t] * Vb[(size_t)t * 64];
    if (vnew && g == (Tc & 3)) a0 += s[Tc] * vnew[(size_t)bh * 64 + vcol];
    red2[tid] = (a0 + a1) + (a2 + a3);
    __syncthreads();
    if (g == 0) {
        float tot = (red2[vcol] + red2[64 + vcol]) + (red2[128 + vcol] + red2[192 + vcol]);
        outv[(size_t)b * 1024 + h * 64 + vcol] = tot * inv;
    }
}

// ---------------- launcher ----------------
extern "C" void kernel_launch(void* const* d_in, const int* in_sizes, int n_in,
                              void* d_out, int out_size)
{
    const float* dec      = (const float*)d_in[0];
    const float* cache_k  = (const float*)d_in[1];
    const float* cache_v  = (const float*)d_in[2];
    const float* enc_k    = (const float*)d_in[3];
    const float* enc_v    = (const float*)d_in[4];
    const uint8_t* slfm   = (const uint8_t*)d_in[5];
    const uint8_t* encm   = (const uint8_t*)d_in[6];
    const float* w_qs_s   = (const float*)d_in[7];
    const float* w_ks_s   = (const float*)d_in[8];
    const float* w_vs_s   = (const float*)d_in[9];
    const float* proj_w_s = (const float*)d_in[10];
    const float* proj_b_s = (const float*)d_in[11];
    const float* ln_g_s   = (const float*)d_in[12];
    const float* ln_b_s   = (const float*)d_in[13];
    const float* w_qs_e   = (const float*)d_in[14];
    const float* proj_w_e = (const float*)d_in[15];
    const float* proj_b_e = (const float*)d_in[16];
    const float* ln_g_e   = (const float*)d_in[17];
    const float* ln_b_e   = (const float*)d_in[18];
    const float* ffn_w1   = (const float*)d_in[19];
    const float* ffn_b1   = (const float*)d_in[20];
    const float* ffn_w2   = (const float*)d_in[21];
    const float* ffn_b2   = (const float*)d_in[22];
    const float* ln_g_f   = (const float*)d_in[23];
    const float* ln_b_f   = (const float*)d_in[24];

    float* out = (float*)d_out;
    float* slf_probs = out + 32 * 1024;                 // [B,H,2048]
    float* enc_probs = slf_probs + 32 * 16 * 2048;      // [B,H,1024]

    float *pP, *pqs, *pknew, *pvnew, *pqe, *pas, *pae, *px1, *px2, *ph;
    cudaGetSymbolAddress((void**)&pP, g_P);
    cudaGetSymbolAddress((void**)&pqs, g_qs);
    cudaGetSymbolAddress((void**)&pknew, g_knew);
    cudaGetSymbolAddress((void**)&pvnew, g_vnew);
    cudaGetSymbolAddress((void**)&pqe, g_qe);
    cudaGetSymbolAddress((void**)&pas, g_attn_s);
    cudaGetSymbolAddress((void**)&pae, g_attn_e);
    cudaGetSymbolAddress((void**)&px1, g_x1);
    cudaGetSymbolAddress((void**)&px2, g_x2);
    cudaGetSymbolAddress((void**)&ph, g_h);

    // q_s / k_new / v_new projections (headed weights, K=1024, split-K 4)
    gemm32<<<dim3(16, 4), NT>>>(dec, w_qs_s, pP, 1024, 1024, 256, 1);
    reduce_sum_k<<<128, NT>>>(pP, pqs, 32768, 32768, 4);
    gemm32<<<dim3(16, 4), NT>>>(dec, w_ks_s, pP, 1024, 1024, 256, 1);
    reduce_sum_k<<<128, NT>>>(pP, pknew, 32768, 32768, 4);
    gemm32<<<dim3(16, 4), NT>>>(dec, w_vs_s, pP, 1024, 1024, 256, 1);
    reduce_sum_k<<<128, NT>>>(pP, pvnew, 32768, 32768, 4);

    // self attention over cache + new token
    attn_kernel<<<512, NT>>>(pqs, cache_k, cache_v, pknew, pvnew, slfm,
                             slf_probs, pas, 2048, 2047);

    // proj + residual + LN
    gemm32<<<dim3(16, 8), NT>>>(pas, proj_w_s, pP, 1024, 1024, 128, 0);
    ln_finish<<<32, NT>>>(pP, 8, proj_b_s, dec, ln_g_s, ln_b_s, px1);

    // cross-attn q projection
    gemm32<<<dim3(16, 4), NT>>>(px1, w_qs_e, pP, 1024, 1024, 256, 1);
    reduce_sum_k<<<128, NT>>>(pP, pqe, 32768, 32768, 4);

    // cross attention
    attn_kernel<<<512, NT>>>(pqe, enc_k, enc_v, nullptr, nullptr, encm,
                             enc_probs, pae, 1024, 1024);

    // proj + residual + LN
    gemm32<<<dim3(16, 8), NT>>>(pae, proj_w_e, pP, 1024, 1024, 128, 0);
    ln_finish<<<32, NT>>>(pP, 8, proj_b_e, px1, ln_g_e, ln_b_e, px2);

    // FFN
    gemm32<<<dim3(64, 4), NT>>>(px2, ffn_w1, pP, 1024, 4096, 256, 0);
    reduce_bias_relu<<<512, NT>>>(pP, ffn_b1, ph, 131072, 131072, 4, 4096);
    gemm32<<<dim3(16, 16), NT>>>(ph, ffn_w2, pP, 4096, 1024, 256, 0);
    ln_finish<<<32, NT>>>(pP, 16, ffn_b2, px2, ln_g_f, ln_b_f, out);
}

// round 9
// speedup vs baseline: 1.3494x; 1.3494x over previous
#include <cuda_runtime.h>
#include <math.h>
#include <stdint.h>

#define NT 256
#define NW 8

// ---------------- scratch (device globals, no allocation) ----------------
__device__ float g_P[524288];      // split-K partials (2MB max)
__device__ float g_qkv[98304];     // fused q/k/v outputs [3][32][1024]
__device__ float g_qe[32768];
__device__ float g_attn_s[32768];
__device__ float g_attn_e[32768];
__device__ float g_x1[32768];
__device__ float g_x2[32768];
__device__ float g_h[131072];      // ffn hidden [32,4096]

// ---------------- fused q/k/v projection (headed weights) ----------------
// A[32,1024]; W[z] is [H=16][1024][64]; P[z][bk][32][1024]
__global__ void gemm_qkv(const float* __restrict__ A,
                         const float* __restrict__ W0,
                         const float* __restrict__ W1,
                         const float* __restrict__ W2,
                         float* __restrict__ P, int kchunk)
{
    __shared__ float As[32][32];
    int bn = blockIdx.x, bk = blockIdx.y, z = blockIdx.z;
    const float* W = (z == 0) ? W0 : (z == 1) ? W1 : W2;
    int tid = threadIdx.x;
    int n = tid & 63, bg = tid >> 6;
    const float* Wt = W + (size_t)bn * 1024 * 64 + n;
    int k0 = bk * kchunk, k1 = k0 + kchunk;
    float acc[8];
    #pragma unroll
    for (int i = 0; i < 8; i++) acc[i] = 0.f;

    for (int kb = k0; kb < k1; kb += 32) {
        __syncthreads();
        for (int i = tid; i < 1024; i += NT) {
            int b = i >> 5, kk = i & 31;
            As[b][kk] = A[(size_t)b * 1024 + kb + kk];
        }
        __syncthreads();
        const float* wp = Wt + (size_t)kb * 64;
        #pragma unroll
        for (int kk = 0; kk < 32; kk++) {
            float w = wp[(size_t)kk * 64];
            #pragma unroll
            for (int i = 0; i < 8; i++) acc[i] += As[bg * 8 + i][kk] * w;
        }
    }
    float* Pz = P + (size_t)z * 131072 + (size_t)bk * 32768;
    #pragma unroll
    for (int i = 0; i < 8; i++)
        Pz[((size_t)bg * 8 + i) * 1024 + (size_t)bn * 64 + n] = acc[i];
}

__global__ void reduce_qkv(const float* __restrict__ P, float* __restrict__ out)
{
    int i = blockIdx.x * blockDim.x + threadIdx.x;   // 98304 total
    int z = i >> 15, r = i & 32767;
    const float* p = P + (size_t)z * 131072 + r;
    out[i] = (p[0] + p[32768]) + (p[65536] + p[98304]);
}

// ---------------- small GEMM: C[32,N] = A[32,K] @ W, split-K partials ----
__global__ void gemm32(const float* __restrict__ A, const float* __restrict__ W,
                       float* __restrict__ P, int K, int N, int kchunk, int headed)
{
    __shared__ float As[32][32];
    int bn = blockIdx.x, bk = blockIdx.y;
    int tid = threadIdx.x;
    int n = tid & 63, bg = tid >> 6;
    const float* Wt;
    size_t ldw;
    if (headed) { Wt = W + (size_t)bn * K * 64 + n; ldw = 64; }
    else        { Wt = W + (size_t)bn * 64 + n;     ldw = (size_t)N; }
    int k0 = bk * kchunk, k1 = min(K, k0 + kchunk);
    float acc[8];
    #pragma unroll
    for (int i = 0; i < 8; i++) acc[i] = 0.f;

    for (int kb = k0; kb < k1; kb += 32) {
        __syncthreads();
        for (int i = tid; i < 1024; i += NT) {
            int b = i >> 5, kk = i & 31;
            As[b][kk] = A[(size_t)b * K + kb + kk];
        }
        __syncthreads();
        const float* wp = Wt + (size_t)kb * ldw;
        #pragma unroll
        for (int kk = 0; kk < 32; kk++) {
            float w = wp[(size_t)kk * ldw];
            #pragma unroll
            for (int i = 0; i < 8; i++) acc[i] += As[bg * 8 + i][kk] * w;
        }
    }
    #pragma unroll
    for (int i = 0; i < 8; i++)
        P[((size_t)bk * 32 + bg * 8 + i) * N + (size_t)bn * 64 + n] = acc[i];
}

__global__ void reduce_sum_k(const float* __restrict__ P, float* __restrict__ out,
                             int total, int stride, int KS)
{
    int i = blockIdx.x * blockDim.x + threadIdx.x;
    if (i >= total) return;
    float v = 0.f;
    for (int s = 0; s < KS; s++) v += P[(size_t)s * stride + i];
    out[i] = v;
}

__global__ void reduce_bias_relu(const float* __restrict__ P, const float* __restrict__ bias,
                                 float* __restrict__ out, int total, int stride, int KS, int N)
{
    int i = blockIdx.x * blockDim.x + threadIdx.x;
    if (i >= total) return;
    float v = bias[i % N];
    for (int s = 0; s < KS; s++) v += P[(size_t)s * stride + i];
    out[i] = fmaxf(v, 0.f);
}

// ---------------- sum partials + bias + residual, then LayerNorm ----------
__global__ void ln_finish(const float* __restrict__ P, int KS,
                          const float* __restrict__ bias, const float* __restrict__ res,
                          const float* __restrict__ gam, const float* __restrict__ bet,
                          float* __restrict__ out)
{
    __shared__ float row[1024];
    __shared__ float redm[NW], redv[NW];
    __shared__ float sh_mean, sh_rstd;
    int b = blockIdx.x, tid = threadIdx.x, lane = tid & 31, wid = tid >> 5;
    float lsum = 0.f, lsq = 0.f;
    for (int c = tid; c < 1024; c += NT) {
        float v = bias[c] + res[(size_t)b * 1024 + c];
        for (int s2 = 0; s2 < KS; s2++)
            v += P[((size_t)s2 * 32 + b) * 1024 + c];
        row[c] = v;
        lsum += v; lsq += v * v;
    }
    #pragma unroll
    for (int o = 16; o; o >>= 1) {
        lsum += __shfl_xor_sync(0xffffffffu, lsum, o);
        lsq  += __shfl_xor_sync(0xffffffffu, lsq, o);
    }
    if (!lane) { redm[wid] = lsum; redv[wid] = lsq; }
    __syncthreads();
    if (wid == 0) {
        float a  = (lane < NW) ? redm[lane] : 0.f;
        float c2 = (lane < NW) ? redv[lane] : 0.f;
        #pragma unroll
        for (int o = 4; o; o >>= 1) {
            a  += __shfl_xor_sync(0xffffffffu, a, o);
            c2 += __shfl_xor_sync(0xffffffffu, c2, o);
        }
        if (!lane) {
            float mean = a * (1.f / 1024.f);
            float var  = c2 * (1.f / 1024.f) - mean * mean;
            sh_mean = mean;
            sh_rstd = rsqrtf(var + 1e-6f);
        }
    }
    __syncthreads();
    float mean = sh_mean, rstd = sh_rstd;
    for (int c = tid; c < 1024; c += NT)
        out[(size_t)b * 1024 + c] = (row[c] - mean) * rstd * gam[c] + bet[c];
}

// ---------------- attention: one block per (b,h), float4 streaming -------
__global__ void attn_kernel(const float* __restrict__ q,
                            const float* __restrict__ Kc,
                            const float* __restrict__ Vc,
                            const float* __restrict__ knew,
                            const float* __restrict__ vnew,
                            const uint8_t* __restrict__ mask,
                            float* __restrict__ probs,
                            float* __restrict__ outv,
                            int T, int Tc)
{
    __shared__ float s[2048];
    __shared__ float red[NW];
    __shared__ float4 red4[256];
    __shared__ float sh_max, sh_sum;
    int bh = blockIdx.x, b = bh >> 4, h = bh & 15;
    int tid = threadIdx.x, lane = tid & 31, wid = tid >> 5;
    size_t base = (size_t)bh * Tc * 64;
    const uint8_t* mrow = mask + (size_t)b * T;
    float4 q4 = reinterpret_cast<const float4*>(q + (size_t)bh * 64)[lane & 15];

    // ---- K phase: warp covers 2 rows per float4 load, 8 rows in flight ----
    float lmax = -INFINITY;
    int half = lane >> 4;                       // 0: even row, 1: odd row
    for (int t0 = wid * 8; t0 < Tc; t0 += NW * 8) {
        float d[4];
        #pragma unroll
        for (int j = 0; j < 4; j++) {
            int r = t0 + 2 * j;
            float4 kv = make_float4(0.f, 0.f, 0.f, 0.f);
            if (r + half < Tc)
                kv = reinterpret_cast<const float4*>(Kc + base + (size_t)r * 64)[lane];
            d[j] = kv.x * q4.x + kv.y * q4.y + kv.z * q4.z + kv.w * q4.w;
        }
        #pragma unroll
        for (int j = 0; j < 4; j++) {
            float v = d[j];
            v += __shfl_xor_sync(0xffffffffu, v, 8);
            v += __shfl_xor_sync(0xffffffffu, v, 4);
            v += __shfl_xor_sync(0xffffffffu, v, 2);
            v += __shfl_xor_sync(0xffffffffu, v, 1);
            int r = t0 + 2 * j + half;
            if ((lane & 15) == 0 && r < Tc) {
                float sc = v * 0.125f;          // 1/sqrt(64)
                if (mrow[r]) sc = -INFINITY;
                s[r] = sc;
                lmax = fmaxf(lmax, sc);
            }
        }
    }
    // ---- new-token key (self-attn only) ----
    if (knew && wid == 0) {
        float4 kv = reinterpret_cast<const float4*>(knew + (size_t)bh * 64)[lane & 15];
        float v = kv.x * q4.x + kv.y * q4.y + kv.z * q4.z + kv.w * q4.w;
        v += __shfl_xor_sync(0xffffffffu, v, 8);
        v += __shfl_xor_sync(0xffffffffu, v, 4);
        v += __shfl_xor_sync(0xffffffffu, v, 2);
        v += __shfl_xor_sync(0xffffffffu, v, 1);
        if (lane == 0) {
            float sc = v * 0.125f;
            if (mrow[Tc]) sc = -INFINITY;
            s[Tc] = sc;
            lmax = fmaxf(lmax, sc);
        }
    }
    // ---- block max ----
    #pragma unroll
    for (int o = 16; o; o >>= 1) lmax = fmaxf(lmax, __shfl_xor_sync(0xffffffffu, lmax, o));
    if (lane == 0) red[wid] = lmax;
    __syncthreads();
    if (wid == 0) {
        float m = (lane < NW) ? red[lane] : -INFINITY;
        #pragma unroll
        for (int o = 4; o; o >>= 1) m = fmaxf(m, __shfl_xor_sync(0xffffffffu, m, o));
        if (lane == 0) sh_max = m;
    }
    __syncthreads();
    float gmax = sh_max;

    // ---- exp + sum ----
    float lsum = 0.f;
    for (int t = tid; t < T; t += NT) {
        float e = __expf(s[t] - gmax);
        s[t] = e;
        lsum += e;
    }
    #pragma unroll
    for (int o = 16; o; o >>= 1) lsum += __shfl_xor_sync(0xffffffffu, lsum, o);
    if (lane == 0) red[wid] = lsum;
    __syncthreads();
    if (wid == 0) {
        float m = (lane < NW) ? red[lane] : 0.f;
        #pragma unroll
        for (int o = 4; o; o >>= 1) m += __shfl_xor_sync(0xffffffffu, m, o);
        if (lane == 0) sh_sum = m;
    }
    __syncthreads();
    float inv = 1.f / sh_sum;

    // ---- write normalized probs ----
    for (int t = tid; t < T; t += NT)
        probs[(size_t)bh * T + t] = s[t] * inv;

    // ---- V phase: 16 groups of 16 lanes, float4, 4 rows in flight ----
    int g = tid >> 4, vl = tid & 15;
    const float4* Vb = reinterpret_cast<const float4*>(Vc + base) + vl;
    float4 a0 = make_float4(0.f,0.f,0.f,0.f), a1 = a0, a2 = a0, a3 = a0;
    int t = g;
    for (; t + 48 < Tc; t += 64) {
        float4 v0 = Vb[(size_t)t * 16];
        float4 v1 = Vb[(size_t)(t + 16) * 16];
        float4 v2 = Vb[(size_t)(t + 32) * 16];
        float4 v3 = Vb[(size_t)(t + 48) * 16];
        float w0 = s[t], w1 = s[t + 16], w2 = s[t + 32], w3 = s[t + 48];
        a0.x += w0 * v0.x; a0.y += w0 * v0.y; a0.z += w0 * v0.z; a0.w += w0 * v0.w;
        a1.x += w1 * v1.x; a1.y += w1 * v1.y; a1.z += w1 * v1.z; a1.w += w1 * v1.w;
        a2.x += w2 * v2.x; a2.y += w2 * v2.y; a2.z += w2 * v2.z; a2.w += w2 * v2.w;
        a3.x += w3 * v3.x; a3.y += w3 * v3.y; a3.z += w3 * v3.z; a3.w += w3 * v3.w;
    }
    for (; t < Tc; t += 16) {
        float4 v0 = Vb[(size_t)t * 16];
        float w0 = s[t];
        a0.x += w0 * v0.x; a0.y += w0 * v0.y; a0.z += w0 * v0.z; a0.w += w0 * v0.w;
    }
    if (vnew && g == (Tc & 15)) {
        float4 vn = reinterpret_cast<const float4*>(vnew + (size_t)bh * 64)[vl];
        float w = s[Tc];
        a0.x += w * vn.x; a0.y += w * vn.y; a0.z += w * vn.z; a0.w += w * vn.w;
    }
    a0.x += a1.x + a2.x + a3.x;
    a0.y += a1.y + a2.y + a3.y;
    a0.z += a1.z + a2.z + a3.z;
    a0.w += a1.w + a2.w + a3.w;
    red4[tid] = a0;
    __syncthreads();
    if (tid < 64) {
        const float* rf = reinterpret_cast<const float*>(red4);
        float tot = 0.f;
        #pragma unroll
        for (int gg = 0; gg < 16; gg++) tot += rf[gg * 64 + tid];
        outv[(size_t)b * 1024 + h * 64 + tid] = tot * inv;
    }
}

// ---------------- launcher ----------------
extern "C" void kernel_launch(void* const* d_in, const int* in_sizes, int n_in,
                              void* d_out, int out_size)
{
    const float* dec      = (const float*)d_in[0];
    const float* cache_k  = (const float*)d_in[1];
    const float* cache_v  = (const float*)d_in[2];
    const float* enc_k    = (const float*)d_in[3];
    const float* enc_v    = (const float*)d_in[4];
    const uint8_t* slfm   = (const uint8_t*)d_in[5];
    const uint8_t* encm   = (const uint8_t*)d_in[6];
    const float* w_qs_s   = (const float*)d_in[7];
    const float* w_ks_s   = (const float*)d_in[8];
    const float* w_vs_s   = (const float*)d_in[9];
    const float* proj_w_s = (const float*)d_in[10];
    const float* proj_b_s = (const float*)d_in[11];
    const float* ln_g_s   = (const float*)d_in[12];
    const float* ln_b_s   = (const float*)d_in[13];
    const float* w_qs_e   = (const float*)d_in[14];
    const float* proj_w_e = (const float*)d_in[15];
    const float* proj_b_e = (const float*)d_in[16];
    const float* ln_g_e   = (const float*)d_in[17];
    const float* ln_b_e   = (const float*)d_in[18];
    const float* ffn_w1   = (const float*)d_in[19];
    const float* ffn_b1   = (const float*)d_in[20];
    const float* ffn_w2   = (const float*)d_in[21];
    const float* ffn_b2   = (const float*)d_in[22];
    const float* ln_g_f   = (const float*)d_in[23];
    const float* ln_b_f   = (const float*)d_in[24];

    float* out = (float*)d_out;
    float* slf_probs = out + 32 * 1024;                 // [B,H,2048]
    float* enc_probs = slf_probs + 32 * 16 * 2048;      // [B,H,1024]

    float *pP, *pqkv, *pqe, *pas, *pae, *px1, *px2, *ph;
    cudaGetSymbolAddress((void**)&pP, g_P);
    cudaGetSymbolAddress((void**)&pqkv, g_qkv);
    cudaGetSymbolAddress((void**)&pqe, g_qe);
    cudaGetSymbolAddress((void**)&pas, g_attn_s);
    cudaGetSymbolAddress((void**)&pae, g_attn_e);
    cudaGetSymbolAddress((void**)&px1, g_x1);
    cudaGetSymbolAddress((void**)&px2, g_x2);
    cudaGetSymbolAddress((void**)&ph, g_h);
    float* pqs   = pqkv;
    float* pknew = pqkv + 32768;
    float* pvnew = pqkv + 65536;

    // fused q/k/v projections (split-K 4)
    gemm_qkv<<<dim3(16, 4, 3), NT>>>(dec, w_qs_s, w_ks_s, w_vs_s, pP, 256);
    reduce_qkv<<<384, NT>>>(pP, pqkv);

    // self attention over cache + new token
    attn_kernel<<<512, NT>>>(pqs, cache_k, cache_v, pknew, pvnew, slfm,
                             slf_probs, pas, 2048, 2047);

    // proj + residual + LN
    gemm32<<<dim3(16, 16), NT>>>(pas, proj_w_s, pP, 1024, 1024, 64, 0);
    ln_finish<<<32, NT>>>(pP, 16, proj_b_s, dec, ln_g_s, ln_b_s, px1);

    // cross-attn q projection
    gemm32<<<dim3(16, 4), NT>>>(px1, w_qs_e, pP, 1024, 1024, 256, 1);
    reduce_sum_k<<<128, NT>>>(pP, pqe, 32768, 32768, 4);

    // cross attention
    attn_kernel<<<512, NT>>>(pqe, enc_k, enc_v, nullptr, nullptr, encm,
                             enc_probs, pae, 1024, 1024);

    // proj + residual + LN
    gemm32<<<dim3(16, 16), NT>>>(pae, proj_w_e, pP, 1024, 1024, 64, 0);
    ln_finish<<<32, NT>>>(pP, 16, proj_b_e, px1, ln_g_e, ln_b_e, px2);

    // FFN
    gemm32<<<dim3(64, 4), NT>>>(px2, ffn_w1, pP, 1024, 4096, 256, 0);
    reduce_bias_relu<<<512, NT>>>(pP, ffn_b1, ph, 131072, 131072, 4, 4096);
    gemm32<<<dim3(16, 16), NT>>>(ph, ffn_w2, pP, 4096, 1024, 256, 0);
    ln_finish<<<32, NT>>>(pP, 16, ffn_b2, px2, ln_g_f, ln_b_f, out);
}

// round 10
// speedup vs baseline: 1.9474x; 1.4431x over previous
#include <cuda_runtime.h>
#include <math.h>
#include <stdint.h>

#define NT 256
#define NW 8

// ---------------- scratch (device globals, no allocation) ----------------
__device__ float g_P[4194304];     // split-K partials (16MB)
__device__ float g_qkv[98304];     // fused q/k/v outputs [3][32][1024]
__device__ float g_qe[32768];
__device__ float g_attn_s[32768];
__device__ float g_attn_e[32768];
__device__ float g_x1[32768];
__device__ float g_x2[32768];
__device__ float g_h[131072];      // ffn hidden [32,4096]

// ---------------- GEMM core: C[32,N] = A[32,K] @ W, split-K partials ----
// N-tile = 256 floats (64 float4 cols), 4 row-groups x 8 rows.
// headed=1: W is [H][K][64] (per-head row-major); headed=0: W is [K][N].
__device__ __forceinline__ void gemm_body(const float* __restrict__ A,
                                          const float* __restrict__ W,
                                          float* __restrict__ P,
                                          int K, int N, int kchunk,
                                          int headed, int bn, int bk)
{
    __shared__ float As[32][32];
    int tid = threadIdx.x, n4 = tid & 63, bg = tid >> 6;
    const float* Wt;
    size_t ldw;
    if (headed) {
        int head = bn * 4 + (n4 >> 4);
        int col  = (n4 & 15) * 4;
        Wt = W + (size_t)head * K * 64 + col;
        ldw = 64;
    } else {
        Wt = W + (size_t)bn * 256 + n4 * 4;
        ldw = (size_t)N;
    }
    int k0 = bk * kchunk, k1 = min(K, k0 + kchunk);
    float4 acc[8];
    #pragma unroll
    for (int i = 0; i < 8; i++) acc[i] = make_float4(0.f, 0.f, 0.f, 0.f);

    for (int kb = k0; kb < k1; kb += 32) {
        __syncthreads();
        for (int i = tid; i < 1024; i += NT) {
            int b = i >> 5, kk = i & 31;
            As[b][kk] = A[(size_t)b * K + kb + kk];
        }
        __syncthreads();
        const float* wp = Wt + (size_t)kb * ldw;
        #pragma unroll
        for (int kk = 0; kk < 32; kk++) {
            float4 w = *reinterpret_cast<const float4*>(wp + (size_t)kk * ldw);
            #pragma unroll
            for (int i = 0; i < 8; i++) {
                float a = As[bg * 8 + i][kk];
                acc[i].x += a * w.x;
                acc[i].y += a * w.y;
                acc[i].z += a * w.z;
                acc[i].w += a * w.w;
            }
        }
    }
    #pragma unroll
    for (int i = 0; i < 8; i++) {
        float* dst = P + ((size_t)bk * 32 + bg * 8 + i) * N + (size_t)bn * 256 + n4 * 4;
        *reinterpret_cast<float4*>(dst) = acc[i];
    }
}

__global__ void gemm32v4(const float* __restrict__ A, const float* __restrict__ W,
                         float* __restrict__ P, int K, int N, int kchunk, int headed)
{
    gemm_body(A, W, P, K, N, kchunk, headed, blockIdx.x, blockIdx.y);
}

// fused q/k/v: z selects weight & partial slab. K=1024, N=1024, headed.
__global__ void gemm_qkv(const float* __restrict__ A,
                         const float* __restrict__ W0,
                         const float* __restrict__ W1,
                         const float* __restrict__ W2,
                         float* __restrict__ P, int kchunk)
{
    int z = blockIdx.z;
    const float* W = (z == 0) ? W0 : (z == 1) ? W1 : W2;
    gemm_body(A, W, P + (size_t)z * 1048576, 1024, 1024, kchunk, 1,
              blockIdx.x, blockIdx.y);
}

__global__ void reduce_qkv(const float* __restrict__ P, float* __restrict__ out)
{
    int i = blockIdx.x * blockDim.x + threadIdx.x;   // 98304 total
    int z = i >> 15, r = i & 32767;
    const float* p = P + (size_t)z * 1048576 + r;
    float v = 0.f;
    #pragma unroll
    for (int s = 0; s < 32; s++) v += p[(size_t)s * 32768];
    out[i] = v;
}

__global__ void reduce_sum_k(const float* __restrict__ P, float* __restrict__ out,
                             int total, int stride, int KS)
{
    int i = blockIdx.x * blockDim.x + threadIdx.x;
    if (i >= total) return;
    float v = 0.f;
    for (int s = 0; s < KS; s++) v += P[(size_t)s * stride + i];
    out[i] = v;
}

__global__ void reduce_bias_relu(const float* __restrict__ P, const float* __restrict__ bias,
                                 float* __restrict__ out, int total, int stride, int KS, int N)
{
    int i = blockIdx.x * blockDim.x + threadIdx.x;
    if (i >= total) return;
    float v = bias[i % N];
    for (int s = 0; s < KS; s++) v += P[(size_t)s * stride + i];
    out[i] = fmaxf(v, 0.f);
}

// ---------------- sum partials + bias + residual, then LayerNorm ----------
__global__ void ln_finish(const float* __restrict__ P, int KS,
                          const float* __restrict__ bias, const float* __restrict__ res,
                          const float* __restrict__ gam, const float* __restrict__ bet,
                          float* __restrict__ out)
{
    __shared__ float row[1024];
    __shared__ float redm[NW], redv[NW];
    __shared__ float sh_mean, sh_rstd;
    int b = blockIdx.x, tid = threadIdx.x, lane = tid & 31, wid = tid >> 5;
    float lsum = 0.f, lsq = 0.f;
    for (int c = tid; c < 1024; c += NT) {
        float v = bias[c] + res[(size_t)b * 1024 + c];
        for (int s2 = 0; s2 < KS; s2++)
            v += P[((size_t)s2 * 32 + b) * 1024 + c];
        row[c] = v;
        lsum += v; lsq += v * v;
    }
    #pragma unroll
    for (int o = 16; o; o >>= 1) {
        lsum += __shfl_xor_sync(0xffffffffu, lsum, o);
        lsq  += __shfl_xor_sync(0xffffffffu, lsq, o);
    }
    if (!lane) { redm[wid] = lsum; redv[wid] = lsq; }
    __syncthreads();
    if (wid == 0) {
        float a  = (lane < NW) ? redm[lane] : 0.f;
        float c2 = (lane < NW) ? redv[lane] : 0.f;
        #pragma unroll
        for (int o = 4; o; o >>= 1) {
            a  += __shfl_xor_sync(0xffffffffu, a, o);
            c2 += __shfl_xor_sync(0xffffffffu, c2, o);
        }
        if (!lane) {
            float mean = a * (1.f / 1024.f);
            float var  = c2 * (1.f / 1024.f) - mean * mean;
            sh_mean = mean;
            sh_rstd = rsqrtf(var + 1e-6f);
        }
    }
    __syncthreads();
    float mean = sh_mean, rstd = sh_rstd;
    for (int c = tid; c < 1024; c += NT)
        out[(size_t)b * 1024 + c] = (row[c] - mean) * rstd * gam[c] + bet[c];
}

// ---------------- attention: one block per (b,h), float4 streaming -------
__global__ void attn_kernel(const float* __restrict__ q,
                            const float* __restrict__ Kc,
                            const float* __restrict__ Vc,
                            const float* __restrict__ knew,
                            const float* __restrict__ vnew,
                            const uint8_t* __restrict__ mask,
                            float* __restrict__ probs,
                            float* __restrict__ outv,
                            int T, int Tc)
{
    __shared__ float s[2048];
    __shared__ float red[NW];
    __shared__ float4 red4[256];
    __shared__ float sh_max, sh_sum;
    int bh = blockIdx.x, b = bh >> 4, h = bh & 15;
    int tid = threadIdx.x, lane = tid & 31, wid = tid >> 5;
    size_t base = (size_t)bh * Tc * 64;
    const uint8_t* mrow = mask + (size_t)b * T;
    float4 q4 = reinterpret_cast<const float4*>(q + (size_t)bh * 64)[lane & 15];

    // ---- K phase: warp covers 2 rows per float4 load, 8 rows in flight ----
    float lmax = -INFINITY;
    int half = lane >> 4;
    for (int t0 = wid * 8; t0 < Tc; t0 += NW * 8) {
        float d[4];
        #pragma unroll
        for (int j = 0; j < 4; j++) {
            int r = t0 + 2 * j;
            float4 kv = make_float4(0.f, 0.f, 0.f, 0.f);
            if (r + half < Tc)
                kv = reinterpret_cast<const float4*>(Kc + base + (size_t)r * 64)[lane];
            d[j] = kv.x * q4.x + kv.y * q4.y + kv.z * q4.z + kv.w * q4.w;
        }
        #pragma unroll
        for (int j = 0; j < 4; j++) {
            float v = d[j];
            v += __shfl_xor_sync(0xffffffffu, v, 8);
            v += __shfl_xor_sync(0xffffffffu, v, 4);
            v += __shfl_xor_sync(0xffffffffu, v, 2);
            v += __shfl_xor_sync(0xffffffffu, v, 1);
            int r = t0 + 2 * j + half;
            if ((lane & 15) == 0 && r < Tc) {
                float sc = v * 0.125f;
                if (mrow[r]) sc = -INFINITY;
                s[r] = sc;
                lmax = fmaxf(lmax, sc);
            }
        }
    }
    if (knew && wid == 0) {
        float4 kv = reinterpret_cast<const float4*>(knew + (size_t)bh * 64)[lane & 15];
        float v = kv.x * q4.x + kv.y * q4.y + kv.z * q4.z + kv.w * q4.w;
        v += __shfl_xor_sync(0xffffffffu, v, 8);
        v += __shfl_xor_sync(0xffffffffu, v, 4);
        v += __shfl_xor_sync(0xffffffffu, v, 2);
        v += __shfl_xor_sync(0xffffffffu, v, 1);
        if (lane == 0) {
            float sc = v * 0.125f;
            if (mrow[Tc]) sc = -INFINITY;
            s[Tc] = sc;
            lmax = fmaxf(lmax, sc);
        }
    }
    #pragma unroll
    for (int o = 16; o; o >>= 1) lmax = fmaxf(lmax, __shfl_xor_sync(0xffffffffu, lmax, o));
    if (lane == 0) red[wid] = lmax;
    __syncthreads();
    if (wid == 0) {
        float m = (lane < NW) ? red[lane] : -INFINITY;
        #pragma unroll
        for (int o = 4; o; o >>= 1) m = fmaxf(m, __shfl_xor_sync(0xffffffffu, m, o));
        if (lane == 0) sh_max = m;
    }
    __syncthreads();
    float gmax = sh_max;

    float lsum = 0.f;
    for (int t = tid; t < T; t += NT) {
        float e = __expf(s[t] - gmax);
        s[t] = e;
        lsum += e;
    }
    #pragma unroll
    for (int o = 16; o; o >>= 1) lsum += __shfl_xor_sync(0xffffffffu, lsum, o);
    if (lane == 0) red[wid] = lsum;
    __syncthreads();
    if (wid == 0) {
        float m = (lane < NW) ? red[lane] : 0.f;
        #pragma unroll
        for (int o = 4; o; o >>= 1) m += __shfl_xor_sync(0xffffffffu, m, o);
        if (lane == 0) sh_sum = m;
    }
    __syncthreads();
    float inv = 1.f / sh_sum;

    for (int t = tid; t < T; t += NT)
        probs[(size_t)bh * T + t] = s[t] * inv;

    // ---- V phase: 16 groups of 16 lanes, float4, 4 rows in flight ----
    int g = tid >> 4, vl = tid & 15;
    const float4* Vb = reinterpret_cast<const float4*>(Vc + base) + vl;
    float4 a0 = make_float4(0.f,0.f,0.f,0.f), a1 = a0, a2 = a0, a3 = a0;
    int t = g;
    for (; t + 48 < Tc; t += 64) {
        float4 v0 = Vb[(size_t)t * 16];
        float4 v1 = Vb[(size_t)(t + 16) * 16];
        float4 v2 = Vb[(size_t)(t + 32) * 16];
        float4 v3 = Vb[(size_t)(t + 48) * 16];
        float w0 = s[t], w1 = s[t + 16], w2 = s[t + 32], w3 = s[t + 48];
        a0.x += w0 * v0.x; a0.y += w0 * v0.y; a0.z += w0 * v0.z; a0.w += w0 * v0.w;
        a1.x += w1 * v1.x; a1.y += w1 * v1.y; a1.z += w1 * v1.z; a1.w += w1 * v1.w;
        a2.x += w2 * v2.x; a2.y += w2 * v2.y; a2.z += w2 * v2.z; a2.w += w2 * v2.w;
        a3.x += w3 * v3.x; a3.y += w3 * v3.y; a3.z += w3 * v3.z; a3.w += w3 * v3.w;
    }
    for (; t < Tc; t += 16) {
        float4 v0 = Vb[(size_t)t * 16];
        float w0 = s[t];
        a0.x += w0 * v0.x; a0.y += w0 * v0.y; a0.z += w0 * v0.z; a0.w += w0 * v0.w;
    }
    if (vnew && g == (Tc & 15)) {
        float4 vn = reinterpret_cast<const float4*>(vnew + (size_t)bh * 64)[vl];
        float w = s[Tc];
        a0.x += w * vn.x; a0.y += w * vn.y; a0.z += w * vn.z; a0.w += w * vn.w;
    }
    a0.x += a1.x + a2.x + a3.x;
    a0.y += a1.y + a2.y + a3.y;
    a0.z += a1.z + a2.z + a3.z;
    a0.w += a1.w + a2.w + a3.w;
    red4[tid] = a0;
    __syncthreads();
    if (tid < 64) {
        const float* rf = reinterpret_cast<const float*>(red4);
        float tot = 0.f;
        #pragma unroll
        for (int gg = 0; gg < 16; gg++) tot += rf[gg * 64 + tid];
        outv[(size_t)b * 1024 + h * 64 + tid] = tot * inv;
    }
}

// ---------------- launcher ----------------
extern "C" void kernel_launch(void* const* d_in, const int* in_sizes, int n_in,
                              void* d_out, int out_size)
{
    const float* dec      = (const float*)d_in[0];
    const float* cache_k  = (const float*)d_in[1];
    const float* cache_v  = (const float*)d_in[2];
    const float* enc_k    = (const float*)d_in[3];
    const float* enc_v    = (const float*)d_in[4];
    const uint8_t* slfm   = (const uint8_t*)d_in[5];
    const uint8_t* encm   = (const uint8_t*)d_in[6];
    const float* w_qs_s   = (const float*)d_in[7];
    const float* w_ks_s   = (const float*)d_in[8];
    const float* w_vs_s   = (const float*)d_in[9];
    const float* proj_w_s = (const float*)d_in[10];
    const float* proj_b_s = (const float*)d_in[11];
    const float* ln_g_s   = (const float*)d_in[12];
    const float* ln_b_s   = (const float*)d_in[13];
    const float* w_qs_e   = (const float*)d_in[14];
    const float* proj_w_e = (const float*)d_in[15];
    const float* proj_b_e = (const float*)d_in[16];
    const float* ln_g_e   = (const float*)d_in[17];
    const float* ln_b_e   = (const float*)d_in[18];
    const float* ffn_w1   = (const float*)d_in[19];
    const float* ffn_b1   = (const float*)d_in[20];
    const float* ffn_w2   = (const float*)d_in[21];
    const float* ffn_b2   = (const float*)d_in[22];
    const float* ln_g_f   = (const float*)d_in[23];
    const float* ln_b_f   = (const float*)d_in[24];

    float* out = (float*)d_out;
    float* slf_probs = out + 32 * 1024;                 // [B,H,2048]
    float* enc_probs = slf_probs + 32 * 16 * 2048;      // [B,H,1024]

    float *pP, *pqkv, *pqe, *pas, *pae, *px1, *px2, *ph;
    cudaGetSymbolAddress((void**)&pP, g_P);
    cudaGetSymbolAddress((void**)&pqkv, g_qkv);
    cudaGetSymbolAddress((void**)&pqe, g_qe);
    cudaGetSymbolAddress((void**)&pas, g_attn_s);
    cudaGetSymbolAddress((void**)&pae, g_attn_e);
    cudaGetSymbolAddress((void**)&px1, g_x1);
    cudaGetSymbolAddress((void**)&px2, g_x2);
    cudaGetSymbolAddress((void**)&ph, g_h);
    float* pqs   = pqkv;
    float* pknew = pqkv + 32768;
    float* pvnew = pqkv + 65536;

    // fused q/k/v projections: 4 n-tiles x 32 split-K x 3 weights = 384 blocks
    gemm_qkv<<<dim3(4, 32, 3), NT>>>(dec, w_qs_s, w_ks_s, w_vs_s, pP, 32);
    reduce_qkv<<<384, NT>>>(pP, pqkv);

    // self attention over cache + new token
    attn_kernel<<<512, NT>>>(pqs, cache_k, cache_v, pknew, pvnew, slfm,
                             slf_probs, pas, 2048, 2047);

    // proj + residual + LN
    gemm32v4<<<dim3(4, 32), NT>>>(pas, proj_w_s, pP, 1024, 1024, 32, 0);
    ln_finish<<<32, NT>>>(pP, 32, proj_b_s, dec, ln_g_s, ln_b_s, px1);

    // cross-attn q projection (headed)
    gemm32v4<<<dim3(4, 16), NT>>>(px1, w_qs_e, pP, 1024, 1024, 64, 1);
    reduce_sum_k<<<128, NT>>>(pP, pqe, 32768, 32768, 16);

    // cross attention
    attn_kernel<<<512, NT>>>(pqe, enc_k, enc_v, nullptr, nullptr, encm,
                             enc_probs, pae, 1024, 1024);

    // proj + residual + LN
    gemm32v4<<<dim3(4, 32), NT>>>(pae, proj_w_e, pP, 1024, 1024, 32, 0);
    ln_finish<<<32, NT>>>(pP, 32, proj_b_e, px1, ln_g_e, ln_b_e, px2);

    // FFN
    gemm32v4<<<dim3(16, 32), NT>>>(px2, ffn_w1, pP, 1024, 4096, 32, 0);
    reduce_bias_relu<<<512, NT>>>(pP, ffn_b1, ph, 131072, 131072, 32, 4096);
    gemm32v4<<<dim3(4, 64), NT>>>(ph, ffn_w2, pP, 4096, 1024, 64, 0);
    ln_finish<<<32, NT>>>(pP, 64, ffn_b2, px2, ln_g_f, ln_b_f, out);
}

// round 11
// speedup vs baseline: 2.2081x; 1.1339x over previous
#include <cuda_runtime.h>
#include <math.h>
#include <stdint.h>

#define NT 256
#define NW 8

// ---------------- scratch (device globals, no allocation) ----------------
__device__ float g_P[4194304];     // split-K partials (16MB)
__device__ float g_qkv[98304];     // fused q/k/v outputs [3][32][1024]
__device__ float g_qe[32768];
__device__ float g_attn_s[32768];
__device__ float g_attn_e[32768];
__device__ float g_x1[32768];
__device__ float g_x2[32768];
__device__ float g_h[131072];      // ffn hidden [32,4096]

// ---------------- GEMM core: C[32,N] = A[32,K] @ W, split-K partials ----
// N-tile = 256 floats (64 float4 cols), 4 row-groups x 8 rows.
// Inner loop prefetches 8 independent float4 weight rows before FMA
// (8 LDG.128 in flight per thread -> latency hidden).
// headed=1: W is [H][K][64]; headed=0: W is [K][N].
__device__ __forceinline__ void gemm_body(const float* __restrict__ A,
                                          const float* __restrict__ W,
                                          float* __restrict__ P,
                                          int K, int N, int kchunk,
                                          int headed, int bn, int bk)
{
    __shared__ float As[32][32];
    int tid = threadIdx.x, n4 = tid & 63, bg = tid >> 6;
    const float* Wt;
    size_t ldw;
    if (headed) {
        int head = bn * 4 + (n4 >> 4);
        int col  = (n4 & 15) * 4;
        Wt = W + (size_t)head * K * 64 + col;
        ldw = 64;
    } else {
        Wt = W + (size_t)bn * 256 + n4 * 4;
        ldw = (size_t)N;
    }
    int k0 = bk * kchunk, k1 = min(K, k0 + kchunk);
    float4 acc[8];
    #pragma unroll
    for (int i = 0; i < 8; i++) acc[i] = make_float4(0.f, 0.f, 0.f, 0.f);

    for (int kb = k0; kb < k1; kb += 32) {
        __syncthreads();
        for (int i = tid; i < 1024; i += NT) {
            int b = i >> 5, kk = i & 31;
            As[b][kk] = A[(size_t)b * K + kb + kk];
        }
        __syncthreads();
        const float* wp = Wt + (size_t)kb * ldw;
        #pragma unroll
        for (int kq = 0; kq < 32; kq += 8) {
            float4 w[8];
            #pragma unroll
            for (int j = 0; j < 8; j++)
                w[j] = *reinterpret_cast<const float4*>(wp + (size_t)(kq + j) * ldw);
            #pragma unroll
            for (int j = 0; j < 8; j++) {
                #pragma unroll
                for (int i = 0; i < 8; i++) {
                    float a = As[bg * 8 + i][kq + j];
                    acc[i].x += a * w[j].x;
                    acc[i].y += a * w[j].y;
                    acc[i].z += a * w[j].z;
                    acc[i].w += a * w[j].w;
                }
            }
        }
    }
    #pragma unroll
    for (int i = 0; i < 8; i++) {
        float* dst = P + ((size_t)bk * 32 + bg * 8 + i) * N + (size_t)bn * 256 + n4 * 4;
        *reinterpret_cast<float4*>(dst) = acc[i];
    }
}

__global__ void __launch_bounds__(NT, 2)
gemm32v4(const float* __restrict__ A, const float* __restrict__ W,
         float* __restrict__ P, int K, int N, int kchunk, int headed)
{
    gemm_body(A, W, P, K, N, kchunk, headed, blockIdx.x, blockIdx.y);
}

// fused q/k/v: z selects weight & partial slab. K=1024, N=1024, headed.
__global__ void __launch_bounds__(NT, 2)
gemm_qkv(const float* __restrict__ A,
         const float* __restrict__ W0,
         const float* __restrict__ W1,
         const float* __restrict__ W2,
         float* __restrict__ P, int kchunk)
{
    int z = blockIdx.z;
    const float* W = (z == 0) ? W0 : (z == 1) ? W1 : W2;
    gemm_body(A, W, P + (size_t)z * 1048576, 1024, 1024, kchunk, 1,
              blockIdx.x, blockIdx.y);
}

__global__ void reduce_qkv(const float* __restrict__ P, float* __restrict__ out)
{
    int i = blockIdx.x * blockDim.x + threadIdx.x;   // 98304 total
    int z = i >> 15, r = i & 32767;
    const float* p = P + (size_t)z * 1048576 + r;
    float v = 0.f;
    #pragma unroll
    for (int s = 0; s < 32; s++) v += p[(size_t)s * 32768];
    out[i] = v;
}

__global__ void reduce_sum_k(const float* __restrict__ P, float* __restrict__ out,
                             int total, int stride, int KS)
{
    int i = blockIdx.x * blockDim.x + threadIdx.x;
    if (i >= total) return;
    float v = 0.f;
    for (int s = 0; s < KS; s++) v += P[(size_t)s * stride + i];
    out[i] = v;
}

__global__ void reduce_bias_relu(const float* __restrict__ P, const float* __restrict__ bias,
                                 float* __restrict__ out, int total, int stride, int KS, int N)
{
    int i = blockIdx.x * blockDim.x + threadIdx.x;
    if (i >= total) return;
    float v = bias[i % N];
    for (int s = 0; s < KS; s++) v += P[(size_t)s * stride + i];
    out[i] = fmaxf(v, 0.f);
}

// ---------------- sum partials + bias + residual, then LayerNorm ----------
__global__ void ln_finish(const float* __restrict__ P, int KS,
                          const float* __restrict__ bias, const float* __restrict__ res,
                          const float* __restrict__ gam, const float* __restrict__ bet,
                          float* __restrict__ out)
{
    __shared__ float row[1024];
    __shared__ float redm[NW], redv[NW];
    __shared__ float sh_mean, sh_rstd;
    int b = blockIdx.x, tid = threadIdx.x, lane = tid & 31, wid = tid >> 5;
    float lsum = 0.f, lsq = 0.f;
    for (int c = tid; c < 1024; c += NT) {
        float v = bias[c] + res[(size_t)b * 1024 + c];
        for (int s2 = 0; s2 < KS; s2++)
            v += P[((size_t)s2 * 32 + b) * 1024 + c];
        row[c] = v;
        lsum += v; lsq += v * v;
    }
    #pragma unroll
    for (int o = 16; o; o >>= 1) {
        lsum += __shfl_xor_sync(0xffffffffu, lsum, o);
        lsq  += __shfl_xor_sync(0xffffffffu, lsq, o);
    }
    if (!lane) { redm[wid] = lsum; redv[wid] = lsq; }
    __syncthreads();
    if (wid == 0) {
        float a  = (lane < NW) ? redm[lane] : 0.f;
        float c2 = (lane < NW) ? redv[lane] : 0.f;
        #pragma unroll
        for (int o = 4; o; o >>= 1) {
            a  += __shfl_xor_sync(0xffffffffu, a, o);
            c2 += __shfl_xor_sync(0xffffffffu, c2, o);
        }
        if (!lane) {
            float mean = a * (1.f / 1024.f);
            float var  = c2 * (1.f / 1024.f) - mean * mean;
            sh_mean = mean;
            sh_rstd = rsqrtf(var + 1e-6f);
        }
    }
    __syncthreads();
    float mean = sh_mean, rstd = sh_rstd;
    for (int c = tid; c < 1024; c += NT)
        out[(size_t)b * 1024 + c] = (row[c] - mean) * rstd * gam[c] + bet[c];
}

// ---------------- attention: one block per (b,h), float4 streaming -------
__global__ void attn_kernel(const float* __restrict__ q,
                            const float* __restrict__ Kc,
                            const float* __restrict__ Vc,
                            const float* __restrict__ knew,
                            const float* __restrict__ vnew,
                            const uint8_t* __restrict__ mask,
                            float* __restrict__ probs,
                            float* __restrict__ outv,
                            int T, int Tc)
{
    __shared__ float s[2048];
    __shared__ float red[NW];
    __shared__ float4 red4[256];
    __shared__ float sh_max, sh_sum;
    int bh = blockIdx.x, b = bh >> 4, h = bh & 15;
    int tid = threadIdx.x, lane = tid & 31, wid = tid >> 5;
    size_t base = (size_t)bh * Tc * 64;
    const uint8_t* mrow = mask + (size_t)b * T;
    float4 q4 = reinterpret_cast<const float4*>(q + (size_t)bh * 64)[lane & 15];

    // ---- K phase: warp covers 2 rows per float4 load, 8 rows in flight ----
    float lmax = -INFINITY;
    int half = lane >> 4;
    for (int t0 = wid * 8; t0 < Tc; t0 += NW * 8) {
        float d[4];
        #pragma unroll
        for (int j = 0; j < 4; j++) {
            int r = t0 + 2 * j;
            float4 kv = make_float4(0.f, 0.f, 0.f, 0.f);
            if (r + half < Tc)
                kv = reinterpret_cast<const float4*>(Kc + base + (size_t)r * 64)[lane];
            d[j] = kv.x * q4.x + kv.y * q4.y + kv.z * q4.z + kv.w * q4.w;
        }
        #pragma unroll
        for (int j = 0; j < 4; j++) {
            float v = d[j];
            v += __shfl_xor_sync(0xffffffffu, v, 8);
            v += __shfl_xor_sync(0xffffffffu, v, 4);
            v += __shfl_xor_sync(0xffffffffu, v, 2);
            v += __shfl_xor_sync(0xffffffffu, v, 1);
            int r = t0 + 2 * j + half;
            if ((lane & 15) == 0 && r < Tc) {
                float sc = v * 0.125f;
                if (mrow[r]) sc = -INFINITY;
                s[r] = sc;
                lmax = fmaxf(lmax, sc);
            }
        }
    }
    if (knew && wid == 0) {
        float4 kv = reinterpret_cast<const float4*>(knew + (size_t)bh * 64)[lane & 15];
        float v = kv.x * q4.x + kv.y * q4.y + kv.z * q4.z + kv.w * q4.w;
        v += __shfl_xor_sync(0xffffffffu, v, 8);
        v += __shfl_xor_sync(0xffffffffu, v, 4);
        v += __shfl_xor_sync(0xffffffffu, v, 2);
        v += __shfl_xor_sync(0xffffffffu, v, 1);
        if (lane == 0) {
            float sc = v * 0.125f;
            if (mrow[Tc]) sc = -INFINITY;
            s[Tc] = sc;
            lmax = fmaxf(lmax, sc);
        }
    }
    #pragma unroll
    for (int o = 16; o; o >>= 1) lmax = fmaxf(lmax, __shfl_xor_sync(0xffffffffu, lmax, o));
    if (lane == 0) red[wid] = lmax;
    __syncthreads();
    if (wid == 0) {
        float m = (lane < NW) ? red[lane] : -INFINITY;
        #pragma unroll
        for (int o = 4; o; o >>= 1) m = fmaxf(m, __shfl_xor_sync(0xffffffffu, m, o));
        if (lane == 0) sh_max = m;
    }
    __syncthreads();
    float gmax = sh_max;

    float lsum = 0.f;
    for (int t = tid; t < T; t += NT) {
        float e = __expf(s[t] - gmax);
        s[t] = e;
        lsum += e;
    }
    #pragma unroll
    for (int o = 16; o; o >>= 1) lsum += __shfl_xor_sync(0xffffffffu, lsum, o);
    if (lane == 0) red[wid] = lsum;
    __syncthreads();
    if (wid == 0) {
        float m = (lane < NW) ? red[lane] : 0.f;
        #pragma unroll
        for (int o = 4; o; o >>= 1) m += __shfl_xor_sync(0xffffffffu, m, o);
        if (lane == 0) sh_sum = m;
    }
    __syncthreads();
    float inv = 1.f / sh_sum;

    for (int t = tid; t < T; t += NT)
        probs[(size_t)bh * T + t] = s[t] * inv;

    // ---- V phase: 16 groups of 16 lanes, float4, 4 rows in flight ----
    int g = tid >> 4, vl = tid & 15;
    const float4* Vb = reinterpret_cast<const float4*>(Vc + base) + vl;
    float4 a0 = make_float4(0.f,0.f,0.f,0.f), a1 = a0, a2 = a0, a3 = a0;
    int t = g;
    for (; t + 48 < Tc; t += 64) {
        float4 v0 = Vb[(size_t)t * 16];
        float4 v1 = Vb[(size_t)(t + 16) * 16];
        float4 v2 = Vb[(size_t)(t + 32) * 16];
        float4 v3 = Vb[(size_t)(t + 48) * 16];
        float w0 = s[t], w1 = s[t + 16], w2 = s[t + 32], w3 = s[t + 48];
        a0.x += w0 * v0.x; a0.y += w0 * v0.y; a0.z += w0 * v0.z; a0.w += w0 * v0.w;
        a1.x += w1 * v1.x; a1.y += w1 * v1.y; a1.z += w1 * v1.z; a1.w += w1 * v1.w;
        a2.x += w2 * v2.x; a2.y += w2 * v2.y; a2.z += w2 * v2.z; a2.w += w2 * v2.w;
        a3.x += w3 * v3.x; a3.y += w3 * v3.y; a3.z += w3 * v3.z; a3.w += w3 * v3.w;
    }
    for (; t < Tc; t += 16) {
        float4 v0 = Vb[(size_t)t * 16];
        float w0 = s[t];
        a0.x += w0 * v0.x; a0.y += w0 * v0.y; a0.z += w0 * v0.z; a0.w += w0 * v0.w;
    }
    if (vnew && g == (Tc & 15)) {
        float4 vn = reinterpret_cast<const float4*>(vnew + (size_t)bh * 64)[vl];
        float w = s[Tc];
        a0.x += w * vn.x; a0.y += w * vn.y; a0.z += w * vn.z; a0.w += w * vn.w;
    }
    a0.x += a1.x + a2.x + a3.x;
    a0.y += a1.y + a2.y + a3.y;
    a0.z += a1.z + a2.z + a3.z;
    a0.w += a1.w + a2.w + a3.w;
    red4[tid] = a0;
    __syncthreads();
    if (tid < 64) {
        const float* rf = reinterpret_cast<const float*>(red4);
        float tot = 0.f;
        #pragma unroll
        for (int gg = 0; gg < 16; gg++) tot += rf[gg * 64 + tid];
        outv[(size_t)b * 1024 + h * 64 + tid] = tot * inv;
    }
}

// ---------------- launcher ----------------
extern "C" void kernel_launch(void* const* d_in, const int* in_sizes, int n_in,
                              void* d_out, int out_size)
{
    const float* dec      = (const float*)d_in[0];
    const float* cache_k  = (const float*)d_in[1];
    const float* cache_v  = (const float*)d_in[2];
    const float* enc_k    = (const float*)d_in[3];
    const float* enc_v    = (const float*)d_in[4];
    const uint8_t* slfm   = (const uint8_t*)d_in[5];
    const uint8_t* encm   = (const uint8_t*)d_in[6];
    const float* w_qs_s   = (const float*)d_in[7];
    const float* w_ks_s   = (const float*)d_in[8];
    const float* w_vs_s   = (const float*)d_in[9];
    const float* proj_w_s = (const float*)d_in[10];
    const float* proj_b_s = (const float*)d_in[11];
    const float* ln_g_s   = (const float*)d_in[12];
    const float* ln_b_s   = (const float*)d_in[13];
    const float* w_qs_e   = (const float*)d_in[14];
    const float* proj_w_e = (const float*)d_in[15];
    const float* proj_b_e = (const float*)d_in[16];
    const float* ln_g_e   = (const float*)d_in[17];
    const float* ln_b_e   = (const float*)d_in[18];
    const float* ffn_w1   = (const float*)d_in[19];
    const float* ffn_b1   = (const float*)d_in[20];
    const float* ffn_w2   = (const float*)d_in[21];
    const float* ffn_b2   = (const float*)d_in[22];
    const float* ln_g_f   = (const float*)d_in[23];
    const float* ln_b_f   = (const float*)d_in[24];

    float* out = (float*)d_out;
    float* slf_probs = out + 32 * 1024;                 // [B,H,2048]
    float* enc_probs = slf_probs + 32 * 16 * 2048;      // [B,H,1024]

    float *pP, *pqkv, *pqe, *pas, *pae, *px1, *px2, *ph;
    cudaGetSymbolAddress((void**)&pP, g_P);
    cudaGetSymbolAddress((void**)&pqkv, g_qkv);
    cudaGetSymbolAddress((void**)&pqe, g_qe);
    cudaGetSymbolAddress((void**)&pas, g_attn_s);
    cudaGetSymbolAddress((void**)&pae, g_attn_e);
    cudaGetSymbolAddress((void**)&px1, g_x1);
    cudaGetSymbolAddress((void**)&px2, g_x2);
    cudaGetSymbolAddress((void**)&ph, g_h);
    float* pqs   = pqkv;
    float* pknew = pqkv + 32768;
    float* pvnew = pqkv + 65536;

    // fused q/k/v projections: 4 n-tiles x 32 split-K x 3 weights = 384 blocks
    gemm_qkv<<<dim3(4, 32, 3), NT>>>(dec, w_qs_s, w_ks_s, w_vs_s, pP, 32);
    reduce_qkv<<<384, NT>>>(pP, pqkv);

    // self attention over cache + new token
    attn_kernel<<<512, NT>>>(pqs, cache_k, cache_v, pknew, pvnew, slfm,
                             slf_probs, pas, 2048, 2047);

    // proj + residual + LN
    gemm32v4<<<dim3(4, 32), NT>>>(pas, proj_w_s, pP, 1024, 1024, 32, 0);
    ln_finish<<<32, NT>>>(pP, 32, proj_b_s, dec, ln_g_s, ln_b_s, px1);

    // cross-attn q projection (headed)
    gemm32v4<<<dim3(4, 32), NT>>>(px1, w_qs_e, pP, 1024, 1024, 32, 1);
    reduce_sum_k<<<128, NT>>>(pP, pqe, 32768, 32768, 32);

    // cross attention
    attn_kernel<<<512, NT>>>(pqe, enc_k, enc_v, nullptr, nullptr, encm,
                             enc_probs, pae, 1024, 1024);

    // proj + residual + LN
    gemm32v4<<<dim3(4, 32), NT>>>(pae, proj_w_e, pP, 1024, 1024, 32, 0);
    ln_finish<<<32, NT>>>(pP, 32, proj_b_e, px1, ln_g_e, ln_b_e, px2);

    // FFN
    gemm32v4<<<dim3(16, 32), NT>>>(px2, ffn_w1, pP, 1024, 4096, 32, 0);
    reduce_bias_relu<<<512, NT>>>(pP, ffn_b1, ph, 131072, 131072, 32, 4096);
    gemm32v4<<<dim3(4, 64), NT>>>(ph, ffn_w2, pP, 4096, 1024, 64, 0);
    ln_finish<<<32, NT>>>(pP, 64, ffn_b2, px2, ln_g_f, ln_b_f, out);
}

// round 12
// speedup vs baseline: 2.2769x; 1.0312x over previous
#include <cuda_runtime.h>
#include <math.h>
#include <stdint.h>

#define NT 256
#define NW 8

// ---------------- scratch (device globals, no allocation) ----------------
__device__ float g_P[4194304];     // split-K partials (16MB)
__device__ float g_qkv[98304];     // fused q/k/v outputs [3][32][1024]
__device__ float g_qe[32768];
__device__ float g_attn_s[32768];
__device__ float g_attn_e[32768];
__device__ float g_x1[32768];
__device__ float g_x2[32768];
__device__ float g_h[131072];      // ffn hidden [32,4096]
__device__ float g_row[32768];     // reduced (pre-LN) rows

// ---------------- GEMM core: C[32,N] = A[32,K] @ W, split-K partials ----
// N-tile = 128 floats (32 float4 cols), 8 row-groups x 4 rows.
// Per thread: 16 acc regs + 8-deep float4 prefetch. ~80 regs -> 3 blocks/SM.
// headed=1: W is [H][K][64]; headed=0: W is [K][N].
__device__ __forceinline__ void gemm_body(const float* __restrict__ A,
                                          const float* __restrict__ W,
                                          float* __restrict__ P,
                                          int K, int N, int kchunk,
                                          int headed, int bn, int bk)
{
    __shared__ float As[32][16];
    int tid = threadIdx.x, n4 = tid & 31, bg = tid >> 5;   // 32 cols, 8 groups
    const float* Wt;
    size_t ldw;
    if (headed) {
        int head = bn * 2 + (n4 >> 4);
        int col  = (n4 & 15) * 4;
        Wt = W + (size_t)head * K * 64 + col;
        ldw = 64;
    } else {
        Wt = W + (size_t)bn * 128 + n4 * 4;
        ldw = (size_t)N;
    }
    int k0 = bk * kchunk, k1 = min(K, k0 + kchunk);
    float4 acc[4];
    #pragma unroll
    for (int i = 0; i < 4; i++) acc[i] = make_float4(0.f, 0.f, 0.f, 0.f);

    for (int kb = k0; kb < k1; kb += 16) {
        __syncthreads();
        #pragma unroll
        for (int i = tid; i < 512; i += NT) {
            int b = i >> 4, kk = i & 15;
            As[b][kk] = A[(size_t)b * K + kb + kk];
        }
        __syncthreads();
        const float* wp = Wt + (size_t)kb * ldw;
        #pragma unroll
        for (int kq = 0; kq < 16; kq += 8) {
            float4 w[8];
            #pragma unroll
            for (int j = 0; j < 8; j++)
                w[j] = *reinterpret_cast<const float4*>(wp + (size_t)(kq + j) * ldw);
            #pragma unroll
            for (int j = 0; j < 8; j++) {
                #pragma unroll
                for (int i = 0; i < 4; i++) {
                    float a = As[bg * 4 + i][kq + j];
                    acc[i].x += a * w[j].x;
                    acc[i].y += a * w[j].y;
                    acc[i].z += a * w[j].z;
                    acc[i].w += a * w[j].w;
                }
            }
        }
    }
    #pragma unroll
    for (int i = 0; i < 4; i++) {
        float* dst = P + ((size_t)bk * 32 + bg * 4 + i) * N + (size_t)bn * 128 + n4 * 4;
        *reinterpret_cast<float4*>(dst) = acc[i];
    }
}

__global__ void __launch_bounds__(NT, 3)
gemm32v4(const float* __restrict__ A, const float* __restrict__ W,
         float* __restrict__ P, int K, int N, int kchunk, int headed)
{
    gemm_body(A, W, P, K, N, kchunk, headed, blockIdx.x, blockIdx.y);
}

// fused q/k/v: z selects weight & partial slab. K=1024, N=1024, headed.
__global__ void __launch_bounds__(NT, 3)
gemm_qkv(const float* __restrict__ A,
         const float* __restrict__ W0,
         const float* __restrict__ W1,
         const float* __restrict__ W2,
         float* __restrict__ P, int kchunk)
{
    int z = blockIdx.z;
    const float* W = (z == 0) ? W0 : (z == 1) ? W1 : W2;
    gemm_body(A, W, P + (size_t)z * 1048576, 1024, 1024, kchunk, 1,
              blockIdx.x, blockIdx.y);
}

__global__ void reduce_qkv(const float* __restrict__ P, float* __restrict__ out)
{
    int i = blockIdx.x * blockDim.x + threadIdx.x;   // 98304 total
    int z = i >> 15, r = i & 32767;
    const float* p = P + (size_t)z * 1048576 + r;
    float v = 0.f;
    #pragma unroll
    for (int s = 0; s < 16; s++) v += p[(size_t)s * 32768];
    out[i] = v;
}

__global__ void reduce_sum_k(const float* __restrict__ P, float* __restrict__ out,
                             int total, int stride, int KS)
{
    int i = blockIdx.x * blockDim.x + threadIdx.x;
    if (i >= total) return;
    float v = 0.f;
    for (int s = 0; s < KS; s++) v += P[(size_t)s * stride + i];
    out[i] = v;
}

__global__ void reduce_bias_relu(const float* __restrict__ P, const float* __restrict__ bias,
                                 float* __restrict__ out, int total, int stride, int KS, int N)
{
    int i = blockIdx.x * blockDim.x + threadIdx.x;
    if (i >= total) return;
    float v = bias[i % N];
    for (int s = 0; s < KS; s++) v += P[(size_t)s * stride + i];
    out[i] = fmaxf(v, 0.f);
}

// sum split-K partials + bias + residual -> row buffer (parallel, 128 blocks)
__global__ void reduce_addres(const float* __restrict__ P, int KS,
                              const float* __restrict__ bias,
                              const float* __restrict__ res,
                              float* __restrict__ out)
{
    int i = blockIdx.x * blockDim.x + threadIdx.x;   // 32768
    float v = bias[i & 1023] + res[i];
    for (int s = 0; s < KS; s++) v += P[(size_t)s * 32768 + i];
    out[i] = v;
}

// ---------------- LayerNorm over pre-reduced rows ----------------
__global__ void ln_norm(const float* __restrict__ row,
                        const float* __restrict__ gam, const float* __restrict__ bet,
                        float* __restrict__ out)
{
    __shared__ float redm[NW], redv[NW];
    __shared__ float sh_mean, sh_rstd;
    int b = blockIdx.x, tid = threadIdx.x, lane = tid & 31, wid = tid >> 5;
    const float* r = row + (size_t)b * 1024;
    float lsum = 0.f, lsq = 0.f;
    float vals[4];
    #pragma unroll
    for (int j = 0; j < 4; j++) {
        float v = r[tid + j * NT];
        vals[j] = v;
        lsum += v; lsq += v * v;
    }
    #pragma unroll
    for (int o = 16; o; o >>= 1) {
        lsum += __shfl_xor_sync(0xffffffffu, lsum, o);
        lsq  += __shfl_xor_sync(0xffffffffu, lsq, o);
    }
    if (!lane) { redm[wid] = lsum; redv[wid] = lsq; }
    __syncthreads();
    if (wid == 0) {
        float a  = (lane < NW) ? redm[lane] : 0.f;
        float c2 = (lane < NW) ? redv[lane] : 0.f;
        #pragma unroll
        for (int o = 4; o; o >>= 1) {
            a  += __shfl_xor_sync(0xffffffffu, a, o);
            c2 += __shfl_xor_sync(0xffffffffu, c2, o);
        }
        if (!lane) {
            float mean = a * (1.f / 1024.f);
            float var  = c2 * (1.f / 1024.f) - mean * mean;
            sh_mean = mean;
            sh_rstd = rsqrtf(var + 1e-6f);
        }
    }
    __syncthreads();
    float mean = sh_mean, rstd = sh_rstd;
    #pragma unroll
    for (int j = 0; j < 4; j++) {
        int c = tid + j * NT;
        out[(size_t)b * 1024 + c] = (vals[j] - mean) * rstd * gam[c] + bet[c];
    }
}

// ---------------- attention: one block per (b,h), float4 streaming -------
__global__ void attn_kernel(const float* __restrict__ q,
                            const float* __restrict__ Kc,
                            const float* __restrict__ Vc,
                            const float* __restrict__ knew,
                            const float* __restrict__ vnew,
                            const uint8_t* __restrict__ mask,
                            float* __restrict__ probs,
                            float* __restrict__ outv,
                            int T, int Tc)
{
    __shared__ float s[2048];
    __shared__ float red[NW];
    __shared__ float4 red4[256];
    __shared__ float sh_max, sh_sum;
    int bh = blockIdx.x, b = bh >> 4, h = bh & 15;
    int tid = threadIdx.x, lane = tid & 31, wid = tid >> 5;
    size_t base = (size_t)bh * Tc * 64;
    const uint8_t* mrow = mask + (size_t)b * T;
    float4 q4 = reinterpret_cast<const float4*>(q + (size_t)bh * 64)[lane & 15];

    // ---- K phase: warp covers 2 rows per float4 load, 8 rows in flight ----
    float lmax = -INFINITY;
    int half = lane >> 4;
    for (int t0 = wid * 8; t0 < Tc; t0 += NW * 8) {
        float d[4];
        #pragma unroll
        for (int j = 0; j < 4; j++) {
            int r = t0 + 2 * j;
            float4 kv = make_float4(0.f, 0.f, 0.f, 0.f);
            if (r + half < Tc)
                kv = reinterpret_cast<const float4*>(Kc + base + (size_t)r * 64)[lane];
            d[j] = kv.x * q4.x + kv.y * q4.y + kv.z * q4.z + kv.w * q4.w;
        }
        #pragma unroll
        for (int j = 0; j < 4; j++) {
            float v = d[j];
            v += __shfl_xor_sync(0xffffffffu, v, 8);
            v += __shfl_xor_sync(0xffffffffu, v, 4);
            v += __shfl_xor_sync(0xffffffffu, v, 2);
            v += __shfl_xor_sync(0xffffffffu, v, 1);
            int r = t0 + 2 * j + half;
            if ((lane & 15) == 0 && r < Tc) {
                float sc = v * 0.125f;
                if (mrow[r]) sc = -INFINITY;
                s[r] = sc;
                lmax = fmaxf(lmax, sc);
            }
        }
    }
    if (knew && wid == 0) {
        float4 kv = reinterpret_cast<const float4*>(knew + (size_t)bh * 64)[lane & 15];
        float v = kv.x * q4.x + kv.y * q4.y + kv.z * q4.z + kv.w * q4.w;
        v += __shfl_xor_sync(0xffffffffu, v, 8);
        v += __shfl_xor_sync(0xffffffffu, v, 4);
        v += __shfl_xor_sync(0xffffffffu, v, 2);
        v += __shfl_xor_sync(0xffffffffu, v, 1);
        if (lane == 0) {
            float sc = v * 0.125f;
            if (mrow[Tc]) sc = -INFINITY;
            s[Tc] = sc;
            lmax = fmaxf(lmax, sc);
        }
    }
    #pragma unroll
    for (int o = 16; o; o >>= 1) lmax = fmaxf(lmax, __shfl_xor_sync(0xffffffffu, lmax, o));
    if (lane == 0) red[wid] = lmax;
    __syncthreads();
    if (wid == 0) {
        float m = (lane < NW) ? red[lane] : -INFINITY;
        #pragma unroll
        for (int o = 4; o; o >>= 1) m = fmaxf(m, __shfl_xor_sync(0xffffffffu, m, o));
        if (lane == 0) sh_max = m;
    }
    __syncthreads();
    float gmax = sh_max;

    float lsum = 0.f;
    for (int t = tid; t < T; t += NT) {
        float e = __expf(s[t] - gmax);
        s[t] = e;
        lsum += e;
    }
    #pragma unroll
    for (int o = 16; o; o >>= 1) lsum += __shfl_xor_sync(0xffffffffu, lsum, o);
    if (lane == 0) red[wid] = lsum;
    __syncthreads();
    if (wid == 0) {
        float m = (lane < NW) ? red[lane] : 0.f;
        #pragma unroll
        for (int o = 4; o; o >>= 1) m += __shfl_xor_sync(0xffffffffu, m, o);
        if (lane == 0) sh_sum = m;
    }
    __syncthreads();
    float inv = 1.f / sh_sum;

    for (int t = tid; t < T; t += NT)
        probs[(size_t)bh * T + t] = s[t] * inv;

    // ---- V phase: 16 groups of 16 lanes, float4, 4 rows in flight ----
    int g = tid >> 4, vl = tid & 15;
    const float4* Vb = reinterpret_cast<const float4*>(Vc + base) + vl;
    float4 a0 = make_float4(0.f,0.f,0.f,0.f), a1 = a0, a2 = a0, a3 = a0;
    int t = g;
    for (; t + 48 < Tc; t += 64) {
        float4 v0 = Vb[(size_t)t * 16];
        float4 v1 = Vb[(size_t)(t + 16) * 16];
        float4 v2 = Vb[(size_t)(t + 32) * 16];
        float4 v3 = Vb[(size_t)(t + 48) * 16];
        float w0 = s[t], w1 = s[t + 16], w2 = s[t + 32], w3 = s[t + 48];
        a0.x += w0 * v0.x; a0.y += w0 * v0.y; a0.z += w0 * v0.z; a0.w += w0 * v0.w;
        a1.x += w1 * v1.x; a1.y += w1 * v1.y; a1.z += w1 * v1.z; a1.w += w1 * v1.w;
        a2.x += w2 * v2.x; a2.y += w2 * v2.y; a2.z += w2 * v2.z; a2.w += w2 * v2.w;
        a3.x += w3 * v3.x; a3.y += w3 * v3.y; a3.z += w3 * v3.z; a3.w += w3 * v3.w;
    }
    for (; t < Tc; t += 16) {
        float4 v0 = Vb[(size_t)t * 16];
        float w0 = s[t];
        a0.x += w0 * v0.x; a0.y += w0 * v0.y; a0.z += w0 * v0.z; a0.w += w0 * v0.w;
    }
    if (vnew && g == (Tc & 15)) {
        float4 vn = reinterpret_cast<const float4*>(vnew + (size_t)bh * 64)[vl];
        float w = s[Tc];
        a0.x += w * vn.x; a0.y += w * vn.y; a0.z += w * vn.z; a0.w += w * vn.w;
    }
    a0.x += a1.x + a2.x + a3.x;
    a0.y += a1.y + a2.y + a3.y;
    a0.z += a1.z + a2.z + a3.z;
    a0.w += a1.w + a2.w + a3.w;
    red4[tid] = a0;
    __syncthreads();
    if (tid < 64) {
        const float* rf = reinterpret_cast<const float*>(red4);
        float tot = 0.f;
        #pragma unroll
        for (int gg = 0; gg < 16; gg++) tot += rf[gg * 64 + tid];
        outv[(size_t)b * 1024 + h * 64 + tid] = tot * inv;
    }
}

// ---------------- launcher ----------------
extern "C" void kernel_launch(void* const* d_in, const int* in_sizes, int n_in,
                              void* d_out, int out_size)
{
    const float* dec      = (const float*)d_in[0];
    const float* cache_k  = (const float*)d_in[1];
    const float* cache_v  = (const float*)d_in[2];
    const float* enc_k    = (const float*)d_in[3];
    const float* enc_v    = (const float*)d_in[4];
    const uint8_t* slfm   = (const uint8_t*)d_in[5];
    const uint8_t* encm   = (const uint8_t*)d_in[6];
    const float* w_qs_s   = (const float*)d_in[7];
    const float* w_ks_s   = (const float*)d_in[8];
    const float* w_vs_s   = (const float*)d_in[9];
    const float* proj_w_s = (const float*)d_in[10];
    const float* proj_b_s = (const float*)d_in[11];
    const float* ln_g_s   = (const float*)d_in[12];
    const float* ln_b_s   = (const float*)d_in[13];
    const float* w_qs_e   = (const float*)d_in[14];
    const float* proj_w_e = (const float*)d_in[15];
    const float* proj_b_e = (const float*)d_in[16];
    const float* ln_g_e   = (const float*)d_in[17];
    const float* ln_b_e   = (const float*)d_in[18];
    const float* ffn_w1   = (const float*)d_in[19];
    const float* ffn_b1   = (const float*)d_in[20];
    const float* ffn_w2   = (const float*)d_in[21];
    const float* ffn_b2   = (const float*)d_in[22];
    const float* ln_g_f   = (const float*)d_in[23];
    const float* ln_b_f   = (const float*)d_in[24];

    float* out = (float*)d_out;
    float* slf_probs = out + 32 * 1024;                 // [B,H,2048]
    float* enc_probs = slf_probs + 32 * 16 * 2048;      // [B,H,1024]

    float *pP, *pqkv, *pqe, *pas, *pae, *px1, *px2, *ph, *prow;
    cudaGetSymbolAddress((void**)&pP, g_P);
    cudaGetSymbolAddress((void**)&pqkv, g_qkv);
    cudaGetSymbolAddress((void**)&pqe, g_qe);
    cudaGetSymbolAddress((void**)&pas, g_attn_s);
    cudaGetSymbolAddress((void**)&pae, g_attn_e);
    cudaGetSymbolAddress((void**)&px1, g_x1);
    cudaGetSymbolAddress((void**)&px2, g_x2);
    cudaGetSymbolAddress((void**)&ph, g_h);
    cudaGetSymbolAddress((void**)&prow, g_row);
    float* pqs   = pqkv;
    float* pknew = pqkv + 32768;
    float* pvnew = pqkv + 65536;

    // fused q/k/v projections: 8 n-tiles x 16 split-K x 3 = 384 blocks
    gemm_qkv<<<dim3(8, 16, 3), NT>>>(dec, w_qs_s, w_ks_s, w_vs_s, pP, 64);
    reduce_qkv<<<384, NT>>>(pP, pqkv);

    // self attention over cache + new token
    attn_kernel<<<512, NT>>>(pqs, cache_k, cache_v, pknew, pvnew, slfm,
                             slf_probs, pas, 2048, 2047);

    // proj + residual + LN  (8 x 32 = 256 blocks)
    gemm32v4<<<dim3(8, 32), NT>>>(pas, proj_w_s, pP, 1024, 1024, 32, 0);
    reduce_addres<<<128, NT>>>(pP, 32, proj_b_s, dec, prow);
    ln_norm<<<32, NT>>>(prow, ln_g_s, ln_b_s, px1);

    // cross-attn q projection (headed, 8 x 32 = 256 blocks)
    gemm32v4<<<dim3(8, 32), NT>>>(px1, w_qs_e, pP, 1024, 1024, 32, 1);
    reduce_sum_k<<<128, NT>>>(pP, pqe, 32768, 32768, 32);

    // cross attention
    attn_kernel<<<512, NT>>>(pqe, enc_k, enc_v, nullptr, nullptr, encm,
                             enc_probs, pae, 1024, 1024);

    // proj + residual + LN
    gemm32v4<<<dim3(8, 32), NT>>>(pae, proj_w_e, pP, 1024, 1024, 32, 0);
    reduce_addres<<<128, NT>>>(pP, 32, proj_b_e, px1, prow);
    ln_norm<<<32, NT>>>(prow, ln_g_e, ln_b_e, px2);

    // FFN: w1 32 n-tiles x 8 splits = 256 blocks; w2 8 x 32 = 256 blocks
    gemm32v4<<<dim3(32, 8), NT>>>(px2, ffn_w1, pP, 1024, 4096, 128, 0);
    reduce_bias_relu<<<512, NT>>>(pP, ffn_b1, ph, 131072, 131072, 8, 4096);
    gemm32v4<<<dim3(8, 32), NT>>>(ph, ffn_w2, pP, 4096, 1024, 128, 0);
    reduce_addres<<<128, NT>>>(pP, 32, ffn_b2, px2, prow);
    ln_norm<<<32, NT>>>(prow, ln_g_f, ln_b_f, out);
}